// round 1
// baseline (speedup 1.0000x reference)
#include <cuda_runtime.h>
#include <math.h>

// Problem constants
// s=4096, b=8, D=1280, H=16, DH=80, W=64, nw=64
// QKV GEMM : M=32768, N=3840, K=1280   (A=x flat, B=qkv_w, both K-major)
// ATTN     : 32768 independent 16x16x80 problems (one per qkv row)
// PROJ GEMM: M=8192,  N=1280, K=5120   (A=attn-out rearranged, B=proj_w)

#define BM 128
#define BN 128
#define BK 16

// Scratch (device globals; no runtime allocation allowed)
__device__ float g_qkv[125829120ull];   // 32768 * 3840
__device__ float g_attn[41943040ull];   // 8192 * 5120

// ---------------------------------------------------------------------------
// C[M,N] = A[M,K] * B[N,K]^T + bias[N]   (both A and B K-contiguous row-major)
// 128x128 block tile, BK=16, 256 threads, 8x8 per thread, double-buffered smem
// ---------------------------------------------------------------------------
__global__ __launch_bounds__(256) void sgemm_nt_bias(
    const float* __restrict__ A, const float* __restrict__ B,
    const float* __restrict__ bias, float* __restrict__ C,
    int M, int N, int K)
{
    __shared__ __align__(16) float As[2][BK][BM + 4];
    __shared__ __align__(16) float Bs[2][BK][BN + 4];

    const int tid  = threadIdx.x;
    const int trow = tid >> 4;        // 0..15
    const int tcol = tid & 15;        // 0..15
    const int lrow = tid >> 2;        // 0..63
    const int lcol = (tid & 3) << 2;  // 0,4,8,12

    const float* Ab = A + (size_t)blockIdx.y * BM * K;
    const float* Bb = B + (size_t)blockIdx.x * BN * K;

    float acc[8][8];
#pragma unroll
    for (int i = 0; i < 8; i++)
#pragma unroll
        for (int j = 0; j < 8; j++) acc[i][j] = 0.f;

    const int nk = K / BK;

    // prologue: tile 0 -> smem buffer 0
    float4 a0 = *(const float4*)(Ab + (size_t)lrow * K + lcol);
    float4 a1 = *(const float4*)(Ab + (size_t)(lrow + 64) * K + lcol);
    float4 b0 = *(const float4*)(Bb + (size_t)lrow * K + lcol);
    float4 b1 = *(const float4*)(Bb + (size_t)(lrow + 64) * K + lcol);
    As[0][lcol + 0][lrow] = a0.x; As[0][lcol + 1][lrow] = a0.y;
    As[0][lcol + 2][lrow] = a0.z; As[0][lcol + 3][lrow] = a0.w;
    As[0][lcol + 0][lrow + 64] = a1.x; As[0][lcol + 1][lrow + 64] = a1.y;
    As[0][lcol + 2][lrow + 64] = a1.z; As[0][lcol + 3][lrow + 64] = a1.w;
    Bs[0][lcol + 0][lrow] = b0.x; Bs[0][lcol + 1][lrow] = b0.y;
    Bs[0][lcol + 2][lrow] = b0.z; Bs[0][lcol + 3][lrow] = b0.w;
    Bs[0][lcol + 0][lrow + 64] = b1.x; Bs[0][lcol + 1][lrow + 64] = b1.y;
    Bs[0][lcol + 2][lrow + 64] = b1.z; Bs[0][lcol + 3][lrow + 64] = b1.w;
    __syncthreads();

    for (int kt = 0; kt < nk; kt++) {
        const int cur = kt & 1;

        if (kt + 1 < nk) {  // prefetch next tile into registers
            const float* Ap = Ab + (size_t)lrow * K + (size_t)(kt + 1) * BK + lcol;
            const float* Bp = Bb + (size_t)lrow * K + (size_t)(kt + 1) * BK + lcol;
            a0 = *(const float4*)Ap;
            a1 = *(const float4*)(Ap + (size_t)64 * K);
            b0 = *(const float4*)Bp;
            b1 = *(const float4*)(Bp + (size_t)64 * K);
        }

#pragma unroll
        for (int k = 0; k < BK; k++) {
            float ar[8], br[8];
            *(float4*)(ar)     = *(const float4*)&As[cur][k][trow * 8];
            *(float4*)(ar + 4) = *(const float4*)&As[cur][k][trow * 8 + 4];
            *(float4*)(br)     = *(const float4*)&Bs[cur][k][tcol * 8];
            *(float4*)(br + 4) = *(const float4*)&Bs[cur][k][tcol * 8 + 4];
#pragma unroll
            for (int i = 0; i < 8; i++)
#pragma unroll
                for (int j = 0; j < 8; j++)
                    acc[i][j] = fmaf(ar[i], br[j], acc[i][j]);
        }

        if (kt + 1 < nk) {  // stage prefetched tile into the other buffer
            const int nxt = cur ^ 1;
            As[nxt][lcol + 0][lrow] = a0.x; As[nxt][lcol + 1][lrow] = a0.y;
            As[nxt][lcol + 2][lrow] = a0.z; As[nxt][lcol + 3][lrow] = a0.w;
            As[nxt][lcol + 0][lrow + 64] = a1.x; As[nxt][lcol + 1][lrow + 64] = a1.y;
            As[nxt][lcol + 2][lrow + 64] = a1.z; As[nxt][lcol + 3][lrow + 64] = a1.w;
            Bs[nxt][lcol + 0][lrow] = b0.x; Bs[nxt][lcol + 1][lrow] = b0.y;
            Bs[nxt][lcol + 2][lrow] = b0.z; Bs[nxt][lcol + 3][lrow] = b0.w;
            Bs[nxt][lcol + 0][lrow + 64] = b1.x; Bs[nxt][lcol + 1][lrow + 64] = b1.y;
            Bs[nxt][lcol + 2][lrow + 64] = b1.z; Bs[nxt][lcol + 3][lrow + 64] = b1.w;
        }
        __syncthreads();
    }

    // epilogue: add bias, vectorized store
    const int crow = blockIdx.y * BM + trow * 8;
    const int ccol = blockIdx.x * BN + tcol * 8;
    float bv[8];
    *(float4*)(bv)     = *(const float4*)(bias + ccol);
    *(float4*)(bv + 4) = *(const float4*)(bias + ccol + 4);
#pragma unroll
    for (int i = 0; i < 8; i++) {
        float* Cp = C + (size_t)(crow + i) * N + ccol;
        float4 o0 = make_float4(acc[i][0] + bv[0], acc[i][1] + bv[1],
                                acc[i][2] + bv[2], acc[i][3] + bv[3]);
        float4 o1 = make_float4(acc[i][4] + bv[4], acc[i][5] + bv[5],
                                acc[i][6] + bv[6], acc[i][7] + bv[7]);
        *(float4*)Cp       = o0;
        *(float4*)(Cp + 4) = o1;
    }
}

// ---------------------------------------------------------------------------
// Windowed attention: one block per qkv row r = (n*64+w)*8 + b.
// Attention over the 16-head axis: S[h,g] = q_h . k_g / sqrt(80),
// softmax over g, O[h,:] = sum_g P[h,g] * v_g.
// Writes directly into the rearranged layout (row (n*16+h)*8+b, col w*80+d).
// ---------------------------------------------------------------------------
__global__ __launch_bounds__(256) void attn_kernel(const float* __restrict__ qkv,
                                                   float* __restrict__ O2)
{
    __shared__ float qs[16 * 84];   // stride 84 to break bank conflicts
    __shared__ float ks[16 * 84];
    __shared__ float vs[16 * 84];
    __shared__ float sc[16][17];

    const int r    = blockIdx.x;    // (n*64+w)*8 + b
    const int b    = r & 7;
    const int sidx = r >> 3;
    const int w    = sidx & 63;
    const int n    = sidx >> 6;
    const int tid  = threadIdx.x;

    const float* row = qkv + (size_t)r * 3840;
    for (int i = tid; i < 1280; i += 256) {
        int h = i / 80, d = i - h * 80;
        qs[h * 84 + d] = row[i];
        ks[h * 84 + d] = row[1280 + i];
        vs[h * 84 + d] = row[2560 + i];
    }
    __syncthreads();

    // scores: one (h,g) pair per thread (256 = 16*16)
    {
        const int h = tid >> 4, g = tid & 15;
        const float* qh = qs + h * 84;
        const float* kg = ks + g * 84;
        float s = 0.f;
#pragma unroll
        for (int d = 0; d < 80; d++) s = fmaf(qh[d], kg[d], s);
        sc[h][g] = s * 0.11180339887498948f;  // 1/sqrt(80)
    }
    __syncthreads();

    // softmax over g (16 rows, one thread each; tiny)
    if (tid < 16) {
        float m = sc[tid][0];
#pragma unroll
        for (int g = 1; g < 16; g++) m = fmaxf(m, sc[tid][g]);
        float sum = 0.f;
#pragma unroll
        for (int g = 0; g < 16; g++) {
            float e = expf(sc[tid][g] - m);
            sc[tid][g] = e;
            sum += e;
        }
        float inv = 1.f / sum;
#pragma unroll
        for (int g = 0; g < 16; g++) sc[tid][g] *= inv;
    }
    __syncthreads();

    // O[h,d] = sum_g P[h,g] * v[g,d]; scatter into rearranged layout
    float* obase = O2 + ((size_t)(n * 16) * 8 + b) * 5120 + (size_t)w * 80;
    for (int i = tid; i < 1280; i += 256) {
        int h = i / 80, d = i - h * 80;
        float o = 0.f;
#pragma unroll
        for (int g = 0; g < 16; g++) o = fmaf(sc[h][g], vs[g * 84 + d], o);
        obase[(size_t)h * 8 * 5120 + d] = o;
    }
}

// ---------------------------------------------------------------------------
// Launcher
// Inputs: 0=x (4096,8,1280) f32, 1=cu_seqlens i64 (ignored), 2=qkv_w (3840,1280),
//         3=qkv_b (3840), 4=proj_w (1280,5120), 5=proj_b (1280)
// Output: (1024, 8, 1280) f32
// ---------------------------------------------------------------------------
extern "C" void kernel_launch(void* const* d_in, const int* in_sizes, int n_in,
                              void* d_out, int out_size)
{
    const float* x      = (const float*)d_in[0];
    const float* qkv_w  = (const float*)d_in[2];
    const float* qkv_b  = (const float*)d_in[3];
    const float* proj_w = (const float*)d_in[4];
    const float* proj_b = (const float*)d_in[5];
    float* out = (float*)d_out;

    float *qkv_buf, *attn_buf;
    cudaGetSymbolAddress((void**)&qkv_buf, g_qkv);
    cudaGetSymbolAddress((void**)&attn_buf, g_attn);

    // 1) QKV projection: (32768 x 1280) @ (3840 x 1280)^T + bias
    sgemm_nt_bias<<<dim3(3840 / BN, 32768 / BM), 256>>>(
        x, qkv_w, qkv_b, qkv_buf, 32768, 3840, 1280);

    // 2) Windowed attention over head axis, scatter to rearranged layout
    attn_kernel<<<32768, 256>>>(qkv_buf, attn_buf);

    // 3) Output projection: (8192 x 5120) @ (1280 x 5120)^T + bias -> d_out
    sgemm_nt_bias<<<dim3(1280 / BN, 8192 / BM), 256>>>(
        attn_buf, proj_w, proj_b, out, 8192, 1280, 5120);
}

// round 2
// speedup vs baseline: 2.1133x; 2.1133x over previous
#include <cuda_runtime.h>
#include <math.h>
#include <stdint.h>

// Problem: s=4096, b=8, D=1280, H=16, DH=80, W=64, nw=64
// QKV GEMM : M=32768, N=3840, K=1280  (NT, both K-major)
// ATTN     : 32768 independent 16x16x80 attention problems
// PROJ GEMM: M=8192,  N=1280, K=5120  (NT)

#define BM 128
#define BN 128
#define BK 16
#define SST 136   // smem row stride (floats): 136 mod 32 = 8 -> conflict-free frags

// Scratch (device globals; no runtime allocation allowed)
__device__ float g_qkv[125829120ull];   // 32768 * 3840
__device__ float g_attn[41943040ull];   // 8192 * 5120

__device__ __forceinline__ uint32_t f2tf32(float x) {
    uint32_t r;
    asm("cvt.rna.tf32.f32 %0, %1;" : "=r"(r) : "f"(x));
    return r;
}

// ---------------------------------------------------------------------------
// C[M,N] = A[M,K] * B[N,K]^T + bias[N], tf32 tensor cores, fp32 accumulate.
// 128x128 block, BK=16, 256 threads (8 warps, 2x4 warp grid, 64x32 warp tile),
// mma.sync.m16n8k8.tf32, double-buffered smem with register prefetch.
// ---------------------------------------------------------------------------
__global__ __launch_bounds__(256) void tgemm_nt_bias(
    const float* __restrict__ A, const float* __restrict__ B,
    const float* __restrict__ bias, float* __restrict__ C,
    int M, int N, int K)
{
    __shared__ uint32_t As[2][BK][SST];
    __shared__ uint32_t Bs[2][BK][SST];

    const int tid  = threadIdx.x;
    const int wid  = tid >> 5;
    const int lane = tid & 31;
    const int grp  = lane >> 2;   // t/4 : 0..7
    const int qid  = lane & 3;    // t%4 : 0..3

    const int warp_m = (wid & 1) * 64;   // 2 warps along M
    const int warp_n = (wid >> 1) * 32;  // 4 warps along N

    const int lrow = tid >> 2;           // 0..63   (global staging)
    const int lcol = (tid & 3) << 2;     // 0,4,8,12

    const float* Ab = A + (size_t)blockIdx.y * BM * K;
    const float* Bb = B + (size_t)blockIdx.x * BN * K;

    float acc[4][4][4];   // [mfrag][nfrag][c0..c3]
#pragma unroll
    for (int i = 0; i < 4; i++)
#pragma unroll
        for (int j = 0; j < 4; j++)
#pragma unroll
            for (int c = 0; c < 4; c++) acc[i][j][c] = 0.f;

    const int nk = K / BK;

    float4 a0, a1, b0, b1;

#define STAGE(bufi)                                                            \
    do {                                                                       \
        As[bufi][lcol + 0][lrow] = f2tf32(a0.x);                               \
        As[bufi][lcol + 1][lrow] = f2tf32(a0.y);                               \
        As[bufi][lcol + 2][lrow] = f2tf32(a0.z);                               \
        As[bufi][lcol + 3][lrow] = f2tf32(a0.w);                               \
        As[bufi][lcol + 0][lrow + 64] = f2tf32(a1.x);                          \
        As[bufi][lcol + 1][lrow + 64] = f2tf32(a1.y);                          \
        As[bufi][lcol + 2][lrow + 64] = f2tf32(a1.z);                          \
        As[bufi][lcol + 3][lrow + 64] = f2tf32(a1.w);                          \
        Bs[bufi][lcol + 0][lrow] = f2tf32(b0.x);                               \
        Bs[bufi][lcol + 1][lrow] = f2tf32(b0.y);                               \
        Bs[bufi][lcol + 2][lrow] = f2tf32(b0.z);                               \
        Bs[bufi][lcol + 3][lrow] = f2tf32(b0.w);                               \
        Bs[bufi][lcol + 0][lrow + 64] = f2tf32(b1.x);                          \
        Bs[bufi][lcol + 1][lrow + 64] = f2tf32(b1.y);                          \
        Bs[bufi][lcol + 2][lrow + 64] = f2tf32(b1.z);                          \
        Bs[bufi][lcol + 3][lrow + 64] = f2tf32(b1.w);                          \
    } while (0)

    // prologue: tile 0
    a0 = *(const float4*)(Ab + (size_t)lrow * K + lcol);
    a1 = *(const float4*)(Ab + (size_t)(lrow + 64) * K + lcol);
    b0 = *(const float4*)(Bb + (size_t)lrow * K + lcol);
    b1 = *(const float4*)(Bb + (size_t)(lrow + 64) * K + lcol);
    STAGE(0);
    __syncthreads();

    for (int kt = 0; kt < nk; kt++) {
        const int cur = kt & 1;

        if (kt + 1 < nk) {
            const float* Ap = Ab + (size_t)lrow * K + (size_t)(kt + 1) * BK + lcol;
            const float* Bp = Bb + (size_t)lrow * K + (size_t)(kt + 1) * BK + lcol;
            a0 = *(const float4*)Ap;
            a1 = *(const float4*)(Ap + (size_t)64 * K);
            b0 = *(const float4*)Bp;
            b1 = *(const float4*)(Bp + (size_t)64 * K);
        }

#pragma unroll
        for (int ks = 0; ks < BK; ks += 8) {
            uint32_t af[4][4];
            uint32_t bf[4][2];
#pragma unroll
            for (int mf = 0; mf < 4; mf++) {
                const int m = warp_m + mf * 16 + grp;
                af[mf][0] = As[cur][ks + qid][m];
                af[mf][1] = As[cur][ks + qid][m + 8];
                af[mf][2] = As[cur][ks + qid + 4][m];
                af[mf][3] = As[cur][ks + qid + 4][m + 8];
            }
#pragma unroll
            for (int nf = 0; nf < 4; nf++) {
                const int n = warp_n + nf * 8 + grp;
                bf[nf][0] = Bs[cur][ks + qid][n];
                bf[nf][1] = Bs[cur][ks + qid + 4][n];
            }
#pragma unroll
            for (int mf = 0; mf < 4; mf++)
#pragma unroll
                for (int nf = 0; nf < 4; nf++) {
                    asm volatile(
                        "mma.sync.aligned.m16n8k8.row.col.f32.tf32.tf32.f32 "
                        "{%0,%1,%2,%3}, {%4,%5,%6,%7}, {%8,%9}, {%0,%1,%2,%3};"
                        : "+f"(acc[mf][nf][0]), "+f"(acc[mf][nf][1]),
                          "+f"(acc[mf][nf][2]), "+f"(acc[mf][nf][3])
                        : "r"(af[mf][0]), "r"(af[mf][1]),
                          "r"(af[mf][2]), "r"(af[mf][3]),
                          "r"(bf[nf][0]), "r"(bf[nf][1]));
                }
        }

        if (kt + 1 < nk) STAGE(cur ^ 1);
        __syncthreads();
    }

    // epilogue: bias + store (c0,c1 contiguous -> float2)
#pragma unroll
    for (int mf = 0; mf < 4; mf++) {
        const int row0 = blockIdx.y * BM + warp_m + mf * 16 + grp;
#pragma unroll
        for (int nf = 0; nf < 4; nf++) {
            const int col = blockIdx.x * BN + warp_n + nf * 8 + qid * 2;
            const float bv0 = bias[col], bv1 = bias[col + 1];
            float2 r0 = make_float2(acc[mf][nf][0] + bv0, acc[mf][nf][1] + bv1);
            float2 r1 = make_float2(acc[mf][nf][2] + bv0, acc[mf][nf][3] + bv1);
            *(float2*)(C + (size_t)row0 * N + col) = r0;
            *(float2*)(C + (size_t)(row0 + 8) * N + col) = r1;
        }
    }
#undef STAGE
}

// ---------------------------------------------------------------------------
// Windowed attention: one block per qkv row r = (n*64+w)*8 + b.
// Attention over the 16-head axis: S[h,g] = q_h . k_g / sqrt(80),
// softmax over g, O[h,:] = sum_g P[h,g] * v_g.
// Writes directly into the rearranged layout (row (n*16+h)*8+b, col w*80+d).
// ---------------------------------------------------------------------------
__global__ __launch_bounds__(256) void attn_kernel(const float* __restrict__ qkv,
                                                   float* __restrict__ O2)
{
    __shared__ float qs[16 * 84];
    __shared__ float ks[16 * 84];
    __shared__ float vs[16 * 84];
    __shared__ float sc[16][17];

    const int r    = blockIdx.x;
    const int b    = r & 7;
    const int sidx = r >> 3;
    const int w    = sidx & 63;
    const int n    = sidx >> 6;
    const int tid  = threadIdx.x;

    const float* row = qkv + (size_t)r * 3840;
    for (int i = tid; i < 1280; i += 256) {
        int h = i / 80, d = i - h * 80;
        qs[h * 84 + d] = row[i];
        ks[h * 84 + d] = row[1280 + i];
        vs[h * 84 + d] = row[2560 + i];
    }
    __syncthreads();

    {
        const int h = tid >> 4, g = tid & 15;
        const float* qh = qs + h * 84;
        const float* kg = ks + g * 84;
        float s = 0.f;
#pragma unroll
        for (int d = 0; d < 80; d++) s = fmaf(qh[d], kg[d], s);
        sc[h][g] = s * 0.11180339887498948f;
    }
    __syncthreads();

    if (tid < 16) {
        float m = sc[tid][0];
#pragma unroll
        for (int g = 1; g < 16; g++) m = fmaxf(m, sc[tid][g]);
        float sum = 0.f;
#pragma unroll
        for (int g = 0; g < 16; g++) {
            float e = expf(sc[tid][g] - m);
            sc[tid][g] = e;
            sum += e;
        }
        float inv = 1.f / sum;
#pragma unroll
        for (int g = 0; g < 16; g++) sc[tid][g] *= inv;
    }
    __syncthreads();

    float* obase = O2 + ((size_t)(n * 16) * 8 + b) * 5120 + (size_t)w * 80;
    for (int i = tid; i < 1280; i += 256) {
        int h = i / 80, d = i - h * 80;
        float o = 0.f;
#pragma unroll
        for (int g = 0; g < 16; g++) o = fmaf(sc[h][g], vs[g * 84 + d], o);
        obase[(size_t)h * 8 * 5120 + d] = o;
    }
}

// ---------------------------------------------------------------------------
// Launcher
// Inputs: 0=x (4096,8,1280) f32, 1=cu_seqlens i64 (ignored), 2=qkv_w (3840,1280),
//         3=qkv_b (3840), 4=proj_w (1280,5120), 5=proj_b (1280)
// Output: (1024, 8, 1280) f32
// ---------------------------------------------------------------------------
extern "C" void kernel_launch(void* const* d_in, const int* in_sizes, int n_in,
                              void* d_out, int out_size)
{
    const float* x      = (const float*)d_in[0];
    const float* qkv_w  = (const float*)d_in[2];
    const float* qkv_b  = (const float*)d_in[3];
    const float* proj_w = (const float*)d_in[4];
    const float* proj_b = (const float*)d_in[5];
    float* out = (float*)d_out;

    float *qkv_buf, *attn_buf;
    cudaGetSymbolAddress((void**)&qkv_buf, g_qkv);
    cudaGetSymbolAddress((void**)&attn_buf, g_attn);

    // 1) QKV projection: (32768 x 1280) @ (3840 x 1280)^T + bias
    tgemm_nt_bias<<<dim3(3840 / BN, 32768 / BM), 256>>>(
        x, qkv_w, qkv_b, qkv_buf, 32768, 3840, 1280);

    // 2) Windowed attention over head axis, scatter to rearranged layout
    attn_kernel<<<32768, 256>>>(qkv_buf, attn_buf);

    // 3) Output projection: (8192 x 5120) @ (1280 x 5120)^T + bias -> d_out
    tgemm_nt_bias<<<dim3(1280 / BN, 8192 / BM), 256>>>(
        attn_buf, proj_w, proj_b, out, 8192, 1280, 5120);
}